// round 6
// baseline (speedup 1.0000x reference)
#include <cuda_runtime.h>

#define B_N   4096
#define S_N   5
#define D_N   64
#define HS_N  961
#define VSA_N 1024
#define LN_EPSF 1e-3f
#define KPAD 72
#define KTOT 1096
#define HSTRIDE 1104   // even, 16B-aligned rows

typedef unsigned long long ull;

__device__ float g_sp[S_N * VSA_N];                // batch-invariant sp rows
__device__ __align__(16) float g_hA[S_N * HSTRIDE];  // hpad[j]
__device__ __align__(16) float g_hB[S_N * HSTRIDE];  // hpad[j+1]

#define FMA2(acc, a, b) \
    asm("fma.rn.f32x2 %0, %1, %2, %0;" : "+l"(acc) : "l"(a), "l"(b))
#define UNPACK2(lo, hi, src) \
    asm("mov.b64 {%0, %1}, %2;" : "=f"(lo), "=f"(hi) : "l"(src))

__device__ __forceinline__ float fast_silu(float x) {
    return x / (1.0f + __expf(-x));
}

// conv for outputs t = 8*tid + r, r = 0..7.
// acc[r] = sum_d x_d * hpad[Kb + d - r],  Kb = 1032 - 8*tid.
// Pairs pw_d = (hpad[Kb+d-1], hpad[Kb+d]) come pre-packed from g_hA/g_hB.
__device__ __forceinline__ void conv_pairs(const float* __restrict__ hA,
                                           const float* __restrict__ hB,
                                           const ull* __restrict__ px,
                                           int tid, float acc[8]) {
    const int Kb = 1032 - (tid << 3);             // even
    const ull* pAu = reinterpret_cast<const ull*>(hA) + (Kb >> 1);       // odd d: pAu[(d-1)>>1]
    const ull* pBu = reinterpret_cast<const ull*>(hB) + (Kb >> 1) - 1;   // even d: pBu[d>>1]
    ull acc2[4] = {0ull, 0ull, 0ull, 0ull};
    ull pw[8];
    // prime pairs for d = -1..-6
    pw[7] = pAu[-1];  pw[5] = pAu[-2];  pw[3] = pAu[-3];
    pw[6] = pBu[-1];  pw[4] = pBu[-2];  pw[2] = pBu[-3];
    #pragma unroll 1
    for (int c = 0; c < 8; ++c) {
        #pragma unroll
        for (int s = 0; s < 8; ++s) {
            ull hw = (s & 1) ? pAu[(s - 1) >> 1] : pBu[s >> 1];
            pw[s] = hw;                         // slot d&7 == s (chunk base multiple of 8)
            ull xx = px[s];                     // broadcast LDS.64: (x_d, x_d)
            FMA2(acc2[0], xx, pw[s]);           // (acc1, acc0) += x_d * (l_{d-1}, l_d)
            FMA2(acc2[1], xx, pw[(s + 6) & 7]); // (acc3, acc2)
            FMA2(acc2[2], xx, pw[(s + 4) & 7]); // (acc5, acc4)
            FMA2(acc2[3], xx, pw[(s + 2) & 7]); // (acc7, acc6)
        }
        pAu += 4; pBu += 4; px += 8;
    }
    UNPACK2(acc[1], acc[0], acc2[0]);
    UNPACK2(acc[3], acc[2], acc2[1]);
    UNPACK2(acc[5], acc[4], acc2[2]);
    UNPACK2(acc[7], acc[6], acc2[3]);
}

// LN helper: block-wide mean / rstd of silu outputs (y[8] per thread)
__device__ __forceinline__ void block_ln_stats(const float y[8], int tid, int lane, int warp,
                                               float* sh_red, float* sh_stats,
                                               float& mu, float& rs) {
    float s1 = 0.f, s2 = 0.f;
    #pragma unroll
    for (int r = 0; r < 8; ++r) { s1 += y[r]; s2 += y[r] * y[r]; }
    #pragma unroll
    for (int o = 16; o > 0; o >>= 1) {
        s1 += __shfl_xor_sync(0xffffffffu, s1, o);
        s2 += __shfl_xor_sync(0xffffffffu, s2, o);
    }
    if (lane == 0) { sh_red[warp] = s1; sh_red[4 + warp] = s2; }
    __syncthreads();
    if (tid == 0) {
        float a = sh_red[0] + sh_red[1] + sh_red[2] + sh_red[3];
        float q = sh_red[4] + sh_red[5] + sh_red[6] + sh_red[7];
        float m = a * (1.f / VSA_N);
        float v = q * (1.f / VSA_N) - m * m;
        sh_stats[0] = m;
        sh_stats[1] = rsqrtf(v + LN_EPSF);
    }
    __syncthreads();
    mu = sh_stats[0];
    rs = sh_stats[1];
}

// ---------------- kernel 0: build g_hA/g_hB + sp rows (one block per i) ----------------
__global__ __launch_bounds__(128)
void sp_kernel(const float* __restrict__ h,
               const float* __restrict__ symbols,
               const float* __restrict__ gamma,
               const float* __restrict__ beta) {
    __shared__ ull sh_px[D_N];
    __shared__ float sh_red[8];
    __shared__ float sh_stats[2];

    const int tid  = threadIdx.x;
    const int lane = tid & 31;
    const int warp = tid >> 5;
    const int i    = blockIdx.x;

    for (int j = tid; j < HSTRIDE; j += 128) {
        int k = j - KPAD;
        float vA = (k >= 0 && k < HS_N) ? h[i * HS_N + k] : 0.f;
        int k1 = k + 1;
        float vB = (k1 >= 0 && k1 < HS_N) ? h[i * HS_N + k1] : 0.f;
        g_hA[i * HSTRIDE + j] = vA;
        g_hB[i * HSTRIDE + j] = vB;
    }
    if (tid < D_N) {
        unsigned u = __float_as_uint(symbols[i * D_N + tid]);
        sh_px[tid] = ((ull)u << 32) | (ull)u;
    }
    __syncthreads();   // orders global h writes + smem for this block

    float acc[8];
    conv_pairs(g_hA + i * HSTRIDE, g_hB + i * HSTRIDE, sh_px, tid, acc);

    float y[8];
    #pragma unroll
    for (int r = 0; r < 8; ++r) y[r] = fast_silu(acc[r]);
    float mu, rs;
    block_ln_stats(y, tid, lane, warp, sh_red, sh_stats, mu, rs);

    const int t0 = tid << 3;
    #pragma unroll
    for (int r = 0; r < 8; ++r) {
        int t = t0 + r;
        g_sp[i * VSA_N + t] = fmaf((y[r] - mu) * rs, gamma[t], beta[t]);
    }
}

// ---------------- main fused kernel: one block per batch element ----------------
__global__ __launch_bounds__(128, 6)
void fused_main(const float* __restrict__ values,
                const float* __restrict__ gamma,
                const float* __restrict__ beta,
                float* __restrict__ out) {
    __shared__ ull  sh_px[S_N * D_N];   // 2560 B: (x_d, x_d) duplicated pairs
    __shared__ float sh_red[8];
    __shared__ float sh_stats[2];
    __shared__ int   sh_negw[4 * 25];
    __shared__ float sh_w[25];

    const int tid  = threadIdx.x;
    const int lane = tid & 31;
    const int warp = tid >> 5;
    const int b    = blockIdx.x;
    const int t0   = tid << 3;

    for (int idx = tid; idx < S_N * D_N; idx += 128) {
        unsigned u = __float_as_uint(values[b * (S_N * D_N) + idx]);
        sh_px[idx] = ((ull)u << 32) | (ull)u;
    }
    __syncthreads();

    // ---- conv + silu + LayerNorm per i -> vp in registers ----
    float vp[S_N * 8];
    #pragma unroll 1
    for (int i = 0; i < S_N; ++i) {
        float acc[8];
        conv_pairs(g_hA + i * HSTRIDE, g_hB + i * HSTRIDE, sh_px + i * D_N, tid, acc);

        float y[8];
        #pragma unroll
        for (int r = 0; r < 8; ++r) y[r] = fast_silu(acc[r]);
        float mu, rs;
        block_ln_stats(y, tid, lane, warp, sh_red, sh_stats, mu, rs);

        float4 g0  = *reinterpret_cast<const float4*>(gamma + t0);
        float4 g1  = *reinterpret_cast<const float4*>(gamma + t0 + 4);
        float4 be0 = *reinterpret_cast<const float4*>(beta + t0);
        float4 be1 = *reinterpret_cast<const float4*>(beta + t0 + 4);
        float gg[8] = {g0.x, g0.y, g0.z, g0.w, g1.x, g1.y, g1.z, g1.w};
        float bb[8] = {be0.x, be0.y, be0.z, be0.w, be1.x, be1.y, be1.z, be1.w};
        #pragma unroll
        for (int r = 0; r < 8; ++r)
            vp[i * 8 + r] = fmaf((y[r] - mu) * rs, gg[r], bb[r]);
    }

    // ---- scores: negative-count via sign-bit XOR over this thread's t0..t0+7 ----
    int neg[25];
    #pragma unroll
    for (int q = 0; q < 25; ++q) neg[q] = 0;
    #pragma unroll 1
    for (int j = 0; j < S_N; ++j) {
        float4 s0 = *reinterpret_cast<const float4*>(g_sp + j * VSA_N + t0);
        float4 s1 = *reinterpret_cast<const float4*>(g_sp + j * VSA_N + t0 + 4);
        float spj[8] = {s0.x, s0.y, s0.z, s0.w, s1.x, s1.y, s1.z, s1.w};
        #pragma unroll
        for (int i = 0; i < S_N; ++i) {
            int cnt = 0;
            #pragma unroll
            for (int r = 0; r < 8; ++r) {
                float v = vp[i * 8 + r];
                float c = v + spj[r];
                cnt += (int)(((unsigned)(__float_as_int(v) ^ __float_as_int(c))) >> 31);
            }
            neg[j * 5 + i] = cnt;
        }
    }
    #pragma unroll
    for (int q = 0; q < 25; ++q) neg[q] = __reduce_add_sync(0xffffffffu, neg[q]);
    if (lane == 0) {
        #pragma unroll
        for (int q = 0; q < 25; ++q) sh_negw[warp * 25 + q] = neg[q];
    }
    __syncthreads();
    if (tid < 25) {
        int tot = sh_negw[tid] + sh_negw[25 + tid] + sh_negw[50 + tid] + sh_negw[75 + tid];
        sh_w[tid] = (float)(VSA_N - 2 * tot) * (1.f / VSA_N);
    }
    __syncthreads();
    if (tid < 5) {   // softmax over i for row j = tid
        float s[5];
        #pragma unroll
        for (int i = 0; i < 5; ++i) s[i] = sh_w[tid * 5 + i];
        float m = s[0];
        #pragma unroll
        for (int i = 1; i < 5; ++i) m = fmaxf(m, s[i]);
        float e[5]; float sum = 0.f;
        #pragma unroll
        for (int i = 0; i < 5; ++i) { e[i] = __expf(s[i] - m); sum += e[i]; }
        float inv = 1.f / sum;
        #pragma unroll
        for (int i = 0; i < 5; ++i) sh_w[tid * 5 + i] = e[i] * inv;
    }
    __syncthreads();

    // ---- att + final silu + vectorized store ----
    float wloc[25];
    #pragma unroll
    for (int q = 0; q < 25; ++q) wloc[q] = sh_w[q];
    const int ob = b * (S_N * VSA_N);
    #pragma unroll 1
    for (int j = 0; j < S_N; ++j) {
        float4 s0 = *reinterpret_cast<const float4*>(g_sp + j * VSA_N + t0);
        float4 s1 = *reinterpret_cast<const float4*>(g_sp + j * VSA_N + t0 + 4);
        float spj[8] = {s0.x, s0.y, s0.z, s0.w, s1.x, s1.y, s1.z, s1.w};
        float o[8];
        #pragma unroll
        for (int r = 0; r < 8; ++r) {
            float a = 0.f;
            #pragma unroll
            for (int i = 0; i < 5; ++i) a = fmaf(wloc[j * 5 + i], vp[i * 8 + r], a);
            o[r] = fast_silu(a * spj[r]);
        }
        *reinterpret_cast<float4*>(out + ob + j * VSA_N + t0)     = make_float4(o[0], o[1], o[2], o[3]);
        *reinterpret_cast<float4*>(out + ob + j * VSA_N + t0 + 4) = make_float4(o[4], o[5], o[6], o[7]);
    }
}

extern "C" void kernel_launch(void* const* d_in, const int* in_sizes, int n_in,
                              void* d_out, int out_size) {
    (void)in_sizes; (void)n_in; (void)out_size;
    const float* values  = (const float*)d_in[0];
    const float* h       = (const float*)d_in[1];
    const float* symbols = (const float*)d_in[2];
    const float* gamma   = (const float*)d_in[3];
    const float* beta    = (const float*)d_in[4];
    float* out = (float*)d_out;

    sp_kernel<<<S_N, 128>>>(h, symbols, gamma, beta);
    fused_main<<<B_N, 128>>>(values, gamma, beta, out);
}